// round 12
// baseline (speedup 1.0000x reference)
#include <cuda_runtime.h>
#include <cuda_fp16.h>
#include <cstdint>

#define DIM  128
#define MAXN 65536
#define MAXE (1 << 20)
#define NB_MAX (MAXN / 1024)

// Scratch (no allocations allowed). Zero-initialized at module load; every
// run re-zeroes g_cnt in scan_local_kernel so replays see a clean histogram.
__device__ float  g_ssrc[MAXN];          // src logit half
__device__ float  g_sdst[MAXN];          // dst logit half + bias
__device__ int    g_cnt[MAXN];           // per-dst degree histogram
__device__ int    g_start[MAXN + 1];     // CSR row offsets (+ sentinel)
__device__ int    g_cursor[MAXN];        // scatter cursors
__device__ int    g_bsum[NB_MAX];        // scan block sums
__device__ int    g_ssorted[MAXE];       // src ids bucketed by dst
__device__ __half g_srch[(size_t)MAXN * DIM];  // fp16 copy of src_feat (halves gather traffic)

// ---------------------------------------------------------------------------
// Kernel 1: degree histogram over dst. 4 edges/thread, int4 loads.
__global__ void hist_kernel(const int* __restrict__ edge_index, int n_edges) {
    int t = blockIdx.x * blockDim.x + threadIdx.x;
    int base = t * 4;
    const int* dst_row = edge_index + n_edges;
    if (base + 4 <= n_edges) {
        int4 d = ((const int4*)dst_row)[t];
        atomicAdd(&g_cnt[d.x], 1);
        atomicAdd(&g_cnt[d.y], 1);
        atomicAdd(&g_cnt[d.z], 1);
        atomicAdd(&g_cnt[d.w], 1);
    } else {
        for (int e = base; e < n_edges; e++)
            atomicAdd(&g_cnt[dst_row[e]], 1);
    }
}

// ---------------------------------------------------------------------------
// Kernel 2: per-block exclusive scan of g_cnt (1024 elems/block). Coalesced.
// Also re-zeroes g_cnt for the next graph replay.
__global__ void scan_local_kernel(int n) {
    int i = blockIdx.x * 1024 + threadIdx.x;
    int lane = threadIdx.x & 31, wid = threadIdx.x >> 5;
    int v = 0;
    if (i < n) {
        v = g_cnt[i];
        g_cnt[i] = 0;                       // reset invariant for next run
    }

    int x = v;
    #pragma unroll
    for (int o = 1; o < 32; o <<= 1) {
        int y = __shfl_up_sync(0xffffffffu, x, o);
        if (lane >= o) x += y;
    }
    __shared__ int wsum[32];
    if (lane == 31) wsum[wid] = x;
    __syncthreads();
    if (wid == 0) {
        int w = wsum[lane];
        #pragma unroll
        for (int o = 1; o < 32; o <<= 1) {
            int y = __shfl_up_sync(0xffffffffu, w, o);
            if (lane >= o) w += y;
        }
        wsum[lane] = w;
    }
    __syncthreads();
    int base = wid ? wsum[wid - 1] : 0;
    int incl = x + base;
    if (i < n) g_start[i] = incl - v;               // local exclusive
    if (threadIdx.x == 1023) g_bsum[blockIdx.x] = incl;
}

// Kernel 3: exclusive scan of block sums — one warp, shfl-based.
__global__ void scan_bsum_kernel(int nb) {
    int lane = threadIdx.x;                  // blockDim.x == 32
    int i0 = 2 * lane, i1 = 2 * lane + 1;
    int e0 = (i0 < nb) ? g_bsum[i0] : 0;
    int e1 = (i1 < nb) ? g_bsum[i1] : 0;
    int s = e0 + e1;

    int x = s;
    #pragma unroll
    for (int o = 1; o < 32; o <<= 1) {
        int y = __shfl_up_sync(0xffffffffu, x, o);
        if (lane >= o) x += y;
    }
    int ex = x - s;                          // exclusive prefix of pair sums
    if (i0 < nb) g_bsum[i0] = ex;
    if (i1 < nb) g_bsum[i1] = ex + e0;
}

// Kernel 4: globalize offsets, init cursors, write sentinel.
__global__ void finalize_kernel(int n, int n_edges) {
    int i = blockIdx.x * blockDim.x + threadIdx.x;
    if (i < n) {
        int s = g_start[i] + g_bsum[i >> 10];
        g_start[i] = s;
        g_cursor[i] = s;
    }
    if (i == 0) g_start[n] = n_edges;
}

// ---------------------------------------------------------------------------
// Kernel 5 (fused, warp-striped): 224-thread blocks (7 warps).
//   warps 0-1: scatter (bucket src ids by dst) — atomic/latency bound.
//   warps 2-6: precompute node logit halves + fp16 src table (reads the src
//              row anyway; the half-row store is nearly free).
__global__ void scatter_precompute_kernel(const int* __restrict__ edge_index,
                                          const float* __restrict__ src_feat,
                                          const float* __restrict__ dst_feat,
                                          const float* __restrict__ att_w,
                                          const float* __restrict__ att_b,
                                          int n_edges, int n_src, int n_dst) {
    int wid = threadIdx.x >> 5;
    int lane = threadIdx.x & 31;

    if (wid < 2) {
        // ---- scatter: 1 edge per thread
        int gw = blockIdx.x * 2 + wid;
        int e = gw * 32 + lane;
        if (e < n_edges) {
            int s = edge_index[e];
            int d = edge_index[n_edges + e];
            int pos = atomicAdd(&g_cursor[d], 1);
            g_ssorted[pos] = s;
        }
    } else {
        // ---- precompute: 1 node row per warp
        int row = blockIdx.x * 5 + (wid - 2);
        int nmax = n_src > n_dst ? n_src : n_dst;
        if (row >= nmax) return;

        float4 w1 = ((const float4*)att_w)[lane];        // W[0:128]
        float4 w2 = ((const float4*)att_w)[32 + lane];   // W[128:256]

        float acc1 = 0.f, acc2 = 0.f;
        if (row < n_src) {
            float4 a = ((const float4*)(src_feat + (size_t)row * DIM))[lane];
            acc1 = a.x * w1.x + a.y * w1.y + a.z * w1.z + a.w * w1.w;
            // fp16 copy of this row: lane owns elements [lane*4, lane*4+4)
            __half2 h0 = __floats2half2_rn(a.x, a.y);
            __half2 h1 = __floats2half2_rn(a.z, a.w);
            uint2 packed;
            packed.x = *(const unsigned int*)&h0;
            packed.y = *(const unsigned int*)&h1;
            ((uint2*)(g_srch + (size_t)row * DIM))[lane] = packed;
        }
        if (row < n_dst) {
            float4 b = ((const float4*)(dst_feat + (size_t)row * DIM))[lane];
            acc2 = b.x * w2.x + b.y * w2.y + b.z * w2.z + b.w * w2.w;
        }
        #pragma unroll
        for (int off = 16; off; off >>= 1) {
            acc1 += __shfl_xor_sync(0xffffffffu, acc1, off);
            acc2 += __shfl_xor_sync(0xffffffffu, acc2, off);
        }
        if (lane == 0) {
            if (row < n_src) g_ssrc[row] = acc1;
            if (row < n_dst) g_sdst[row] = acc2 + att_b[0];
        }
    }
}

// ---------------------------------------------------------------------------
// Kernel 6: one warp per dst row. fp16 gather (256 B/row, half the LTS
// traffic), fp32 gates/accumulate/normalize, single fp32 write.
__global__ void aggregate_kernel(float* __restrict__ out, int n_dst) {
    int warp = (blockIdx.x * blockDim.x + threadIdx.x) >> 5;
    int lane = threadIdx.x & 31;
    if (warp >= n_dst) return;

    int beg = g_start[warp], end = g_start[warp + 1];
    float sd = g_sdst[warp];

    float4 acc = make_float4(0.f, 0.f, 0.f, 0.f);
    float csum = 0.f;

    int i = beg;
    for (; i + 2 <= end; i += 2) {
        int s0 = g_ssorted[i];
        int s1 = g_ssorted[i + 1];
        float a0 = 1.f / (1.f + __expf(-(g_ssrc[s0] + sd)));
        float a1 = 1.f / (1.f + __expf(-(g_ssrc[s1] + sd)));
        uint2 p0 = ((const uint2*)(g_srch + (size_t)s0 * DIM))[lane];
        uint2 p1 = ((const uint2*)(g_srch + (size_t)s1 * DIM))[lane];
        float2 v0a = __half22float2(*(const __half2*)&p0.x);
        float2 v0b = __half22float2(*(const __half2*)&p0.y);
        float2 v1a = __half22float2(*(const __half2*)&p1.x);
        float2 v1b = __half22float2(*(const __half2*)&p1.y);
        acc.x += a0 * v0a.x + a1 * v1a.x;
        acc.y += a0 * v0a.y + a1 * v1a.y;
        acc.z += a0 * v0b.x + a1 * v1b.x;
        acc.w += a0 * v0b.y + a1 * v1b.y;
        csum += a0 + a1;
    }
    if (i < end) {
        int s0 = g_ssorted[i];
        float a0 = 1.f / (1.f + __expf(-(g_ssrc[s0] + sd)));
        uint2 p0 = ((const uint2*)(g_srch + (size_t)s0 * DIM))[lane];
        float2 v0a = __half22float2(*(const __half2*)&p0.x);
        float2 v0b = __half22float2(*(const __half2*)&p0.y);
        acc.x += a0 * v0a.x; acc.y += a0 * v0a.y;
        acc.z += a0 * v0b.x; acc.w += a0 * v0b.y;
        csum += a0;
    }

    float inv = 1.f / fmaxf(csum, 1e-8f);
    ((float4*)(out + (size_t)warp * DIM))[lane] =
        make_float4(acc.x * inv, acc.y * inv, acc.z * inv, acc.w * inv);
}

// ---------------------------------------------------------------------------
extern "C" void kernel_launch(void* const* d_in, const int* in_sizes, int n_in,
                              void* d_out, int out_size) {
    const float* src_feat = (const float*)d_in[0];
    const float* dst_feat = (const float*)d_in[1];
    const float* att_w    = (const float*)d_in[2];
    const float* att_b    = (const float*)d_in[3];
    const int*   edge_idx = (const int*)d_in[4];   // int32 (JAX x64 disabled)

    int n_src   = in_sizes[0] / DIM;
    int n_dst   = out_size / DIM;
    int n_edges = in_sizes[4] / 2;
    float* out  = (float*)d_out;

    int nmax = n_src > n_dst ? n_src : n_dst;
    int nb = (n_dst + 1023) / 1024;

    // Kernel 1: histogram
    {
        int t = (n_edges + 3) / 4;
        hist_kernel<<<(t + 255) / 256, 256>>>(edge_idx, n_edges);
    }
    // Kernels 2-4: scan chain
    scan_local_kernel<<<nb, 1024>>>(n_dst);
    scan_bsum_kernel<<<1, 32>>>(nb);
    finalize_kernel<<<(n_dst + 255) / 256, 256>>>(n_dst, n_edges);
    // Kernel 5: scatter (2 warps/blk) + precompute + fp16 table (5 warps/blk)
    {
        int sw = (n_edges + 31) / 32;          // scatter warps
        int nw = nmax;                          // precompute warps
        int b1 = (sw + 1) / 2, b2 = (nw + 4) / 5;
        int blocks = b1 > b2 ? b1 : b2;
        scatter_precompute_kernel<<<blocks, 224>>>(edge_idx, src_feat, dst_feat,
                                                   att_w, att_b,
                                                   n_edges, n_src, n_dst);
    }
    // Kernel 6: aggregate (fp16 gather)
    aggregate_kernel<<<(n_dst * 32 + 255) / 256, 256>>>(out, n_dst);
}

// round 13
// speedup vs baseline: 1.4789x; 1.4789x over previous
#include <cuda_runtime.h>
#include <cstdint>

#define DIM  128
#define MAXN 65536
#define MAXE (1 << 20)
#define NB_MAX (MAXN / 1024 + 1)

// Scratch (no allocations allowed). Zero-initialized at module load; every
// run re-zeroes g_cnt in scan_local_kernel so replays see a clean histogram.
__device__ float g_ssrc[MAXN];          // src logit half
__device__ float g_sdst[MAXN];          // dst logit half + bias
__device__ int   g_cnt[MAXN];           // per-dst degree histogram
__device__ int   g_start[MAXN + 1];     // CSR row offsets, LOCAL-exclusive (+ sentinel)
__device__ int   g_cursor[MAXN];        // scatter cursors, LOCAL-exclusive
__device__ int   g_bsum[NB_MAX];        // per-1024-block global base offsets
__device__ int   g_ssorted[MAXE];       // src ids bucketed by dst

// ---------------------------------------------------------------------------
// Kernel 1: degree histogram over dst. 4 edges/thread, int4 loads.
__global__ void hist_kernel(const int* __restrict__ edge_index, int n_edges) {
    int t = blockIdx.x * blockDim.x + threadIdx.x;
    int base = t * 4;
    const int* dst_row = edge_index + n_edges;
    if (base + 4 <= n_edges) {
        int4 d = ((const int4*)dst_row)[t];
        atomicAdd(&g_cnt[d.x], 1);
        atomicAdd(&g_cnt[d.y], 1);
        atomicAdd(&g_cnt[d.z], 1);
        atomicAdd(&g_cnt[d.w], 1);
    } else {
        for (int e = base; e < n_edges; e++)
            atomicAdd(&g_cnt[dst_row[e]], 1);
    }
}

// ---------------------------------------------------------------------------
// Kernel 2: per-block exclusive scan of g_cnt (1024 elems/block). Coalesced.
// Writes LOCAL-exclusive offsets into both g_start and g_cursor (consumers
// add g_bsum[i>>10] themselves — finalize kernel eliminated). Re-zeroes
// g_cnt for the next graph replay. i<=n so the sentinel's local value lands.
__global__ void scan_local_kernel(int n) {
    int i = blockIdx.x * 1024 + threadIdx.x;
    int lane = threadIdx.x & 31, wid = threadIdx.x >> 5;
    int v = 0;
    if (i < n) {
        v = g_cnt[i];
        g_cnt[i] = 0;                       // reset invariant for next run
    }

    int x = v;
    #pragma unroll
    for (int o = 1; o < 32; o <<= 1) {
        int y = __shfl_up_sync(0xffffffffu, x, o);
        if (lane >= o) x += y;
    }
    __shared__ int wsum[32];
    if (lane == 31) wsum[wid] = x;
    __syncthreads();
    if (wid == 0) {
        int w = wsum[lane];
        #pragma unroll
        for (int o = 1; o < 32; o <<= 1) {
            int y = __shfl_up_sync(0xffffffffu, w, o);
            if (lane >= o) w += y;
        }
        wsum[lane] = w;
    }
    __syncthreads();
    int base = wid ? wsum[wid - 1] : 0;
    int incl = x + base;
    int excl = incl - v;                     // local exclusive
    if (i <= n) g_start[i] = excl;
    if (i < n)  g_cursor[i] = excl;
    if (threadIdx.x == 1023) g_bsum[blockIdx.x] = incl;
}

// Kernel 3: exclusive scan of block sums — one warp, shfl-based.
__global__ void scan_bsum_kernel(int nb) {
    int lane = threadIdx.x;                  // blockDim.x == 32
    int i0 = 2 * lane, i1 = 2 * lane + 1;
    int e0 = (i0 < nb) ? g_bsum[i0] : 0;
    int e1 = (i1 < nb) ? g_bsum[i1] : 0;
    int s = e0 + e1;

    int x = s;
    #pragma unroll
    for (int o = 1; o < 32; o <<= 1) {
        int y = __shfl_up_sync(0xffffffffu, x, o);
        if (lane >= o) x += y;
    }
    int ex = x - s;                          // exclusive prefix of pair sums
    if (i0 < nb) g_bsum[i0] = ex;
    if (i1 < nb) g_bsum[i1] = ex + e0;
}

// ---------------------------------------------------------------------------
// Kernel 4 (fused, warp-striped): 224-thread blocks (7 warps).
//   warps 0-1: scatter (bucket src ids by dst) — atomic/latency bound.
//   warps 2-6: precompute node logit halves   — DRAM-stream bound.
__global__ void scatter_precompute_kernel(const int* __restrict__ edge_index,
                                          const float* __restrict__ src_feat,
                                          const float* __restrict__ dst_feat,
                                          const float* __restrict__ att_w,
                                          const float* __restrict__ att_b,
                                          int n_edges, int n_src, int n_dst) {
    int wid = threadIdx.x >> 5;
    int lane = threadIdx.x & 31;

    if (wid < 2) {
        // ---- scatter: 1 edge per thread; global pos = local cursor + block base
        int gw = blockIdx.x * 2 + wid;
        int e = gw * 32 + lane;
        if (e < n_edges) {
            int s = edge_index[e];
            int d = edge_index[n_edges + e];
            int pos = atomicAdd(&g_cursor[d], 1) + g_bsum[d >> 10];
            g_ssorted[pos] = s;
        }
    } else {
        // ---- precompute: 1 node row per warp
        int row = blockIdx.x * 5 + (wid - 2);
        int nmax = n_src > n_dst ? n_src : n_dst;
        if (row >= nmax) return;

        float4 w1 = ((const float4*)att_w)[lane];        // W[0:128]
        float4 w2 = ((const float4*)att_w)[32 + lane];   // W[128:256]

        float acc1 = 0.f, acc2 = 0.f;
        if (row < n_src) {
            float4 a = ((const float4*)(src_feat + (size_t)row * DIM))[lane];
            acc1 = a.x * w1.x + a.y * w1.y + a.z * w1.z + a.w * w1.w;
        }
        if (row < n_dst) {
            float4 b = ((const float4*)(dst_feat + (size_t)row * DIM))[lane];
            acc2 = b.x * w2.x + b.y * w2.y + b.z * w2.z + b.w * w2.w;
        }
        #pragma unroll
        for (int off = 16; off; off >>= 1) {
            acc1 += __shfl_xor_sync(0xffffffffu, acc1, off);
            acc2 += __shfl_xor_sync(0xffffffffu, acc2, off);
        }
        if (lane == 0) {
            if (row < n_src) g_ssrc[row] = acc1;
            if (row < n_dst) g_sdst[row] = acc2 + att_b[0];
        }
    }
}

// ---------------------------------------------------------------------------
// Kernel 5: one warp per dst row. Register accumulation, fused normalize,
// single write. 2-way manual MLP on the gathers. beg/end = local + block base.
__global__ void aggregate_kernel(const float* __restrict__ src_feat,
                                 float* __restrict__ out, int n_dst) {
    int warp = (blockIdx.x * blockDim.x + threadIdx.x) >> 5;
    int lane = threadIdx.x & 31;
    if (warp >= n_dst) return;

    int beg = g_start[warp]     + g_bsum[warp >> 10];
    int end = g_start[warp + 1] + g_bsum[(warp + 1) >> 10];
    float sd = g_sdst[warp];

    float4 acc = make_float4(0.f, 0.f, 0.f, 0.f);
    float csum = 0.f;

    int i = beg;
    for (; i + 2 <= end; i += 2) {
        int s0 = g_ssorted[i];
        int s1 = g_ssorted[i + 1];
        float a0 = 1.f / (1.f + __expf(-(g_ssrc[s0] + sd)));
        float a1 = 1.f / (1.f + __expf(-(g_ssrc[s1] + sd)));
        float4 v0 = ((const float4*)(src_feat + (size_t)s0 * DIM))[lane];
        float4 v1 = ((const float4*)(src_feat + (size_t)s1 * DIM))[lane];
        acc.x += a0 * v0.x + a1 * v1.x;
        acc.y += a0 * v0.y + a1 * v1.y;
        acc.z += a0 * v0.z + a1 * v1.z;
        acc.w += a0 * v0.w + a1 * v1.w;
        csum += a0 + a1;
    }
    if (i < end) {
        int s0 = g_ssorted[i];
        float a0 = 1.f / (1.f + __expf(-(g_ssrc[s0] + sd)));
        float4 v0 = ((const float4*)(src_feat + (size_t)s0 * DIM))[lane];
        acc.x += a0 * v0.x; acc.y += a0 * v0.y;
        acc.z += a0 * v0.z; acc.w += a0 * v0.w;
        csum += a0;
    }

    float inv = 1.f / fmaxf(csum, 1e-8f);
    ((float4*)(out + (size_t)warp * DIM))[lane] =
        make_float4(acc.x * inv, acc.y * inv, acc.z * inv, acc.w * inv);
}

// ---------------------------------------------------------------------------
extern "C" void kernel_launch(void* const* d_in, const int* in_sizes, int n_in,
                              void* d_out, int out_size) {
    const float* src_feat = (const float*)d_in[0];
    const float* dst_feat = (const float*)d_in[1];
    const float* att_w    = (const float*)d_in[2];
    const float* att_b    = (const float*)d_in[3];
    const int*   edge_idx = (const int*)d_in[4];   // int32 (JAX x64 disabled)

    int n_src   = in_sizes[0] / DIM;
    int n_dst   = out_size / DIM;
    int n_edges = in_sizes[4] / 2;
    float* out  = (float*)d_out;

    int nmax = n_src > n_dst ? n_src : n_dst;
    int nb = (n_dst + 1023) / 1024;

    // Kernel 1: histogram
    {
        int t = (n_edges + 3) / 4;
        hist_kernel<<<(t + 255) / 256, 256>>>(edge_idx, n_edges);
    }
    // Kernels 2-3: scan chain (finalize eliminated; consumers add g_bsum)
    scan_local_kernel<<<nb, 1024>>>(n_dst);
    scan_bsum_kernel<<<1, 32>>>(nb);
    // Kernel 4: scatter (2 warps/blk) + precompute (5 warps/blk), striped
    {
        int sw = (n_edges + 31) / 32;          // scatter warps
        int nw = nmax;                          // precompute warps
        int b1 = (sw + 1) / 2, b2 = (nw + 4) / 5;
        int blocks = b1 > b2 ? b1 : b2;
        scatter_precompute_kernel<<<blocks, 224>>>(edge_idx, src_feat, dst_feat,
                                                   att_w, att_b,
                                                   n_edges, n_src, n_dst);
    }
    // Kernel 5: aggregate
    aggregate_kernel<<<(n_dst * 32 + 255) / 256, 256>>>(src_feat, out, n_dst);
}